// round 5
// baseline (speedup 1.0000x reference)
#include <cuda_runtime.h>
#include <cuda_fp16.h>

#define M_TOTAL 4096
#define N_TOTAL 11008
#define K_TOTAL 4096

// Scratch: fp16 copies of x and unpacked integer weights (exact in fp16).
__device__ __align__(16) __half g_x[(size_t)M_TOTAL * K_TOTAL];   // 33.5 MB
__device__ __align__(16) __half g_w[(size_t)N_TOTAL * K_TOTAL];   // 90.2 MB

// ---------------------------------------------------------------------------
// Pre-pass 1: x fp32 -> fp16 (8 floats / thread)
// ---------------------------------------------------------------------------
__global__ void convert_x_kernel(const float* __restrict__ x) {
    int i = blockIdx.x * blockDim.x + threadIdx.x;
    const float4* xv = (const float4*)x;
    float4 a = xv[2 * i];
    float4 b = xv[2 * i + 1];
    __half2 h0 = __floats2half2_rn(a.x, a.y);
    __half2 h1 = __floats2half2_rn(a.z, a.w);
    __half2 h2 = __floats2half2_rn(b.x, b.y);
    __half2 h3 = __floats2half2_rn(b.z, b.w);
    uint4 u;
    u.x = *(const unsigned int*)&h0;
    u.y = *(const unsigned int*)&h1;
    u.z = *(const unsigned int*)&h2;
    u.w = *(const unsigned int*)&h3;
    ((uint4*)g_x)[i] = u;
}

// ---------------------------------------------------------------------------
// Pre-pass 2: unpack int4 nibbles -> fp16 integers (exact; scale in epilogue)
// ---------------------------------------------------------------------------
__device__ __forceinline__ __half2 unpack_pair(int v) {
    int lo = (v & 15) - 8;
    int hi = ((v >> 4) & 15) - 8;
    return __halves2half2(__int2half_rn(lo), __int2half_rn(hi));
}

__global__ void convert_w_kernel(const int* __restrict__ wp) {
    int i = blockIdx.x * blockDim.x + threadIdx.x;
    int4 p = ((const int4*)wp)[i];
    __half2 h0 = unpack_pair(p.x);
    __half2 h1 = unpack_pair(p.y);
    __half2 h2 = unpack_pair(p.z);
    __half2 h3 = unpack_pair(p.w);
    uint4 u;
    u.x = *(const unsigned int*)&h0;
    u.y = *(const unsigned int*)&h1;
    u.z = *(const unsigned int*)&h2;
    u.w = *(const unsigned int*)&h3;
    ((uint4*)g_w)[i] = u;
}

// ---------------------------------------------------------------------------
// GEMM: C[M,N] = Xh[M,K] * Wh[N,K]^T, fp16 in, fp32 acc, mma.sync m16n8k16.
// Block tile 128x256x64, warp tile 64x64 (2x4 warps), 3-stage cp.async
// pipeline (2 stages in flight), register ping-pong over 4 k16 sub-steps,
// ONE __syncthreads per 64-wide k-step. GM=8 supertile swizzle.
// ---------------------------------------------------------------------------
#define BM 128
#define BN 256
#define BK 64
#define STAGES 3
#define KT (K_TOTAL / BK)          // 64
#define AST 72                     // padded row stride in halves (144B)
#define ASTAGE (BM * AST)          // 9216 halves
#define BSTAGE (BN * AST)          // 18432 halves

__device__ __forceinline__ void cp_async16(void* smem_p, const void* gmem) {
    unsigned int s = (unsigned int)__cvta_generic_to_shared(smem_p);
    asm volatile("cp.async.cg.shared.global [%0], [%1], 16;\n" :: "r"(s), "l"(gmem));
}

// A fragments: 4 m16 tiles, ldmatrix.x4 each, at k-substep ks (0..3).
__device__ __forceinline__ void frag_a_load(unsigned int a[4][4],
                                            const __half* A, int wm,
                                            int lane, int ks) {
    #pragma unroll
    for (int mt = 0; mt < 4; mt++) {
        int r  = wm + mt * 16 + (lane & 15);
        int kk = ks * 16 + ((lane >> 4) << 3);
        unsigned int addr = (unsigned int)__cvta_generic_to_shared(&A[r * AST + kk]);
        asm volatile("ldmatrix.sync.aligned.m8n8.x4.shared.b16 {%0,%1,%2,%3}, [%4];"
                     : "=r"(a[mt][0]), "=r"(a[mt][1]), "=r"(a[mt][2]), "=r"(a[mt][3])
                     : "r"(addr));
    }
}

// B fragments: 8 n8 tiles, one ldmatrix.x4 per pair of n8 tiles.
__device__ __forceinline__ void frag_b_load(unsigned int b[8][2],
                                            const __half* B, int wn,
                                            int lane, int ks) {
    #pragma unroll
    for (int np = 0; np < 4; np++) {
        int r  = wn + np * 16 + (((lane >> 4) & 1) << 3) + (lane & 7);
        int kk = ks * 16 + (((lane >> 3) & 1) << 3);
        unsigned int addr = (unsigned int)__cvta_generic_to_shared(&B[r * AST + kk]);
        asm volatile("ldmatrix.sync.aligned.m8n8.x4.shared.b16 {%0,%1,%2,%3}, [%4];"
                     : "=r"(b[2 * np][0]), "=r"(b[2 * np][1]),
                       "=r"(b[2 * np + 1][0]), "=r"(b[2 * np + 1][1])
                     : "r"(addr));
    }
}

__device__ __forceinline__ void mma_tile(float acc[4][8][4],
                                         const unsigned int a[4][4],
                                         const unsigned int b[8][2]) {
    #pragma unroll
    for (int mt = 0; mt < 4; mt++) {
        #pragma unroll
        for (int nt = 0; nt < 8; nt++) {
            asm volatile(
                "mma.sync.aligned.m16n8k16.row.col.f32.f16.f16.f32 "
                "{%0,%1,%2,%3}, {%4,%5,%6,%7}, {%8,%9}, {%0,%1,%2,%3};"
                : "+f"(acc[mt][nt][0]), "+f"(acc[mt][nt][1]),
                  "+f"(acc[mt][nt][2]), "+f"(acc[mt][nt][3])
                : "r"(a[mt][0]), "r"(a[mt][1]), "r"(a[mt][2]), "r"(a[mt][3]),
                  "r"(b[nt][0]), "r"(b[nt][1]));
        }
    }
}

__global__ __launch_bounds__(256, 1)
void gemm_f16_kernel(const float* __restrict__ scale,
                     const float* __restrict__ bias,
                     float* __restrict__ out) {
    extern __shared__ __half smem[];
    __half* As = smem;                       // STAGES * ASTAGE halves
    __half* Bs = smem + STAGES * ASTAGE;     // STAGES * BSTAGE halves

    const int tid  = threadIdx.x;
    const int lane = tid & 31;
    const int warp = tid >> 5;
    const int wm   = (warp >> 2) * 64;
    const int wn   = (warp & 3) * 64;

    // Supertile swizzle: 8 consecutive CTAs share one N-tile.
    const int PN = N_TOTAL / BN;             // 43
    const int GM = 8;
    int pid   = blockIdx.x;
    int group = pid / (GM * PN);
    int rem   = pid % (GM * PN);
    const int m0 = (group * GM + (rem % GM)) * BM;
    const int n0 = (rem / GM) * BN;

    float acc[4][8][4];
    #pragma unroll
    for (int i = 0; i < 4; i++)
        #pragma unroll
        for (int j = 0; j < 8; j++)
            #pragma unroll
            for (int r = 0; r < 4; r++) acc[i][j][r] = 0.0f;

    // Tile loader: A 1024 + B 2048 16B-chunks per stage; 4 + 8 per thread.
    auto load_tiles = [&](int buf, int kbase) {
        #pragma unroll
        for (int j = 0; j < 4; j++) {
            int c   = tid + j * 256;
            int row = c >> 3;
            int ko  = (c & 7) * 8;
            cp_async16(&As[buf * ASTAGE + row * AST + ko],
                       &g_x[(size_t)(m0 + row) * K_TOTAL + kbase + ko]);
        }
        #pragma unroll
        for (int j = 0; j < 8; j++) {
            int c   = tid + j * 256;
            int row = c >> 3;
            int ko  = (c & 7) * 8;
            cp_async16(&Bs[buf * BSTAGE + row * AST + ko],
                       &g_w[(size_t)(n0 + row) * K_TOTAL + kbase + ko]);
        }
    };

    // Prologue: fill 2 stages, wait for stage 0.
    load_tiles(0, 0);
    asm volatile("cp.async.commit_group;\n");
    load_tiles(1, BK);
    asm volatile("cp.async.commit_group;\n");
    asm volatile("cp.async.wait_group 1;\n");
    __syncthreads();

    unsigned int a0[4][4], b0[8][2], a1[4][4], b1[8][2];
    int rs = 0;
    frag_a_load(a0, &As[0], wm, lane, 0);
    frag_b_load(b0, &Bs[0], wn, lane, 0);

    for (int kt = 0; kt < KT; kt++) {
        // ks = 0: prefetch next stage's gmem tiles, frags for ks=1
        frag_a_load(a1, &As[rs * ASTAGE], wm, lane, 1);
        frag_b_load(b1, &Bs[rs * BSTAGE], wn, lane, 1);
        if (kt + 2 < KT) load_tiles((rs + 2) % STAGES, (kt + 2) * BK);
        asm volatile("cp.async.commit_group;\n");
        mma_tile(acc, a0, b0);

        // ks = 1
        frag_a_load(a0, &As[rs * ASTAGE], wm, lane, 2);
        frag_b_load(b0, &Bs[rs * BSTAGE], wn, lane, 2);
        mma_tile(acc, a1, b1);

        // ks = 2
        frag_a_load(a1, &As[rs * ASTAGE], wm, lane, 3);
        frag_b_load(b1, &Bs[rs * BSTAGE], wn, lane, 3);
        mma_tile(acc, a0, b0);

        // ks = 3: rotate to next stage; frags for its ks=0
        if (kt + 1 < KT) {
            asm volatile("cp.async.wait_group 1;\n");
            __syncthreads();
            rs = (rs + 1 == STAGES) ? 0 : rs + 1;
            frag_a_load(a0, &As[rs * ASTAGE], wm, lane, 0);
            frag_b_load(b0, &Bs[rs * BSTAGE], wn, lane, 0);
        }
        mma_tile(acc, a1, b1);
    }

    // --- epilogue: out = acc * scale[n] + bias[n] ---
    const int g = lane >> 2;
    const int t = lane & 3;
    #pragma unroll
    for (int nt = 0; nt < 8; nt++) {
        const int col = n0 + wn + nt * 8 + t * 2;
        const float s0 = __ldg(&scale[col]);
        const float s1 = __ldg(&scale[col + 1]);
        const float bb0 = __ldg(&bias[col]);
        const float bb1 = __ldg(&bias[col + 1]);
        #pragma unroll
        for (int mt = 0; mt < 4; mt++) {
            const int row0 = m0 + wm + mt * 16 + g;
            float2 v0, v1;
            v0.x = acc[mt][nt][0] * s0 + bb0;
            v0.y = acc[mt][nt][1] * s1 + bb1;
            v1.x = acc[mt][nt][2] * s0 + bb0;
            v1.y = acc[mt][nt][3] * s1 + bb1;
            *(float2*)&out[(size_t)row0 * N_TOTAL + col] = v0;
            *(float2*)&out[(size_t)(row0 + 8) * N_TOTAL + col] = v1;
        }
    }
}

// ---------------------------------------------------------------------------
extern "C" void kernel_launch(void* const* d_in, const int* in_sizes, int n_in,
                              void* d_out, int out_size) {
    const float* x     = (const float*)d_in[0];
    const int*   wp    = (const int*)d_in[1];
    const float* scale = (const float*)d_in[2];
    const float* bias  = (const float*)d_in[3];
    float*       out   = (float*)d_out;

    convert_x_kernel<<<8192, 256>>>(x);
    convert_w_kernel<<<22016, 256>>>(wp);

    const int smem_bytes = STAGES * (ASTAGE + BSTAGE) * sizeof(__half);  // 165888
    cudaFuncSetAttribute(gemm_f16_kernel,
                         cudaFuncAttributeMaxDynamicSharedMemorySize, smem_bytes);
    const int grid = (M_TOTAL / BM) * (N_TOTAL / BN);   // 1376
    gemm_f16_kernel<<<grid, 256, smem_bytes>>>(scale, bias, out);
}

// round 6
// speedup vs baseline: 1.0850x; 1.0850x over previous
#include <cuda_runtime.h>
#include <cuda_fp16.h>

#define M_TOTAL 4096
#define N_TOTAL 11008
#define K_TOTAL 4096

// Scratch: fp16 copies of x and unpacked integer weights (exact in fp16).
__device__ __align__(16) __half g_x[(size_t)M_TOTAL * K_TOTAL];   // 33.5 MB
__device__ __align__(16) __half g_w[(size_t)N_TOTAL * K_TOTAL];   // 90.2 MB

// ---------------------------------------------------------------------------
// Pre-pass 1: x fp32 -> fp16 (8 floats / thread)
// ---------------------------------------------------------------------------
__global__ void convert_x_kernel(const float* __restrict__ x) {
    int i = blockIdx.x * blockDim.x + threadIdx.x;
    const float4* xv = (const float4*)x;
    float4 a = xv[2 * i];
    float4 b = xv[2 * i + 1];
    __half2 h0 = __floats2half2_rn(a.x, a.y);
    __half2 h1 = __floats2half2_rn(a.z, a.w);
    __half2 h2 = __floats2half2_rn(b.x, b.y);
    __half2 h3 = __floats2half2_rn(b.z, b.w);
    uint4 u;
    u.x = *(const unsigned int*)&h0;
    u.y = *(const unsigned int*)&h1;
    u.z = *(const unsigned int*)&h2;
    u.w = *(const unsigned int*)&h3;
    ((uint4*)g_x)[i] = u;
}

// ---------------------------------------------------------------------------
// Pre-pass 2: unpack int4 nibbles -> fp16 integers (exact; scale in epilogue)
// 8 int32 per thread for deeper MLP.
// ---------------------------------------------------------------------------
__device__ __forceinline__ __half2 unpack_pair(int v) {
    int lo = (v & 15) - 8;
    int hi = ((v >> 4) & 15) - 8;
    return __halves2half2(__int2half_rn(lo), __int2half_rn(hi));
}

__global__ void convert_w_kernel(const int* __restrict__ wp) {
    int i = blockIdx.x * blockDim.x + threadIdx.x;
    int4 p0 = ((const int4*)wp)[2 * i];
    int4 p1 = ((const int4*)wp)[2 * i + 1];
    uint4 u0, u1;
    {
        __half2 h0 = unpack_pair(p0.x), h1 = unpack_pair(p0.y);
        __half2 h2 = unpack_pair(p0.z), h3 = unpack_pair(p0.w);
        u0.x = *(const unsigned int*)&h0; u0.y = *(const unsigned int*)&h1;
        u0.z = *(const unsigned int*)&h2; u0.w = *(const unsigned int*)&h3;
    }
    {
        __half2 h0 = unpack_pair(p1.x), h1 = unpack_pair(p1.y);
        __half2 h2 = unpack_pair(p1.z), h3 = unpack_pair(p1.w);
        u1.x = *(const unsigned int*)&h0; u1.y = *(const unsigned int*)&h1;
        u1.z = *(const unsigned int*)&h2; u1.w = *(const unsigned int*)&h3;
    }
    ((uint4*)g_w)[2 * i]     = u0;
    ((uint4*)g_w)[2 * i + 1] = u1;
}

// ---------------------------------------------------------------------------
// GEMM: C[M,N] = Xh[M,K] * Wh[N,K]^T, fp16 in, fp32 acc, mma.sync m16n8k16.
// Block tile 128x256x32, warp tile 64x64 (2x4 warps), 5-stage cp.async
// pipeline (3 tiles in flight), register double-buffered fragments,
// GM=16 supertile swizzle.
// ---------------------------------------------------------------------------
#define BM 128
#define BN 256
#define BK 32
#define STAGES 5
#define KT (K_TOTAL / BK)          // 128
#define AST 40                     // padded row stride in halves (80B)
#define ASTAGE (BM * AST)          // 5120 halves
#define BSTAGE (BN * AST)          // 10240 halves

__device__ __forceinline__ void cp_async16(void* smem_p, const void* gmem) {
    unsigned int s = (unsigned int)__cvta_generic_to_shared(smem_p);
    asm volatile("cp.async.cg.shared.global [%0], [%1], 16;\n" :: "r"(s), "l"(gmem));
}

// A fragments: 4 m16 tiles, ldmatrix.x4 each.
__device__ __forceinline__ void frag_a_load(unsigned int a[4][4],
                                            const __half* A, int wm,
                                            int lane, int ks) {
    #pragma unroll
    for (int mt = 0; mt < 4; mt++) {
        int r  = wm + mt * 16 + (lane & 15);
        int kk = ks * 16 + ((lane >> 4) << 3);
        unsigned int addr = (unsigned int)__cvta_generic_to_shared(&A[r * AST + kk]);
        asm volatile("ldmatrix.sync.aligned.m8n8.x4.shared.b16 {%0,%1,%2,%3}, [%4];"
                     : "=r"(a[mt][0]), "=r"(a[mt][1]), "=r"(a[mt][2]), "=r"(a[mt][3])
                     : "r"(addr));
    }
}

// B fragments: 8 n8 tiles, one ldmatrix.x4 per pair of n8 tiles.
__device__ __forceinline__ void frag_b_load(unsigned int b[8][2],
                                            const __half* B, int wn,
                                            int lane, int ks) {
    #pragma unroll
    for (int np = 0; np < 4; np++) {
        int r  = wn + np * 16 + (((lane >> 4) & 1) << 3) + (lane & 7);
        int kk = ks * 16 + (((lane >> 3) & 1) << 3);
        unsigned int addr = (unsigned int)__cvta_generic_to_shared(&B[r * AST + kk]);
        asm volatile("ldmatrix.sync.aligned.m8n8.x4.shared.b16 {%0,%1,%2,%3}, [%4];"
                     : "=r"(b[2 * np][0]), "=r"(b[2 * np][1]),
                       "=r"(b[2 * np + 1][0]), "=r"(b[2 * np + 1][1])
                     : "r"(addr));
    }
}

__device__ __forceinline__ void mma_tile(float acc[4][8][4],
                                         const unsigned int a[4][4],
                                         const unsigned int b[8][2]) {
    #pragma unroll
    for (int mt = 0; mt < 4; mt++) {
        #pragma unroll
        for (int nt = 0; nt < 8; nt++) {
            asm volatile(
                "mma.sync.aligned.m16n8k16.row.col.f32.f16.f16.f32 "
                "{%0,%1,%2,%3}, {%4,%5,%6,%7}, {%8,%9}, {%0,%1,%2,%3};"
                : "+f"(acc[mt][nt][0]), "+f"(acc[mt][nt][1]),
                  "+f"(acc[mt][nt][2]), "+f"(acc[mt][nt][3])
                : "r"(a[mt][0]), "r"(a[mt][1]), "r"(a[mt][2]), "r"(a[mt][3]),
                  "r"(b[nt][0]), "r"(b[nt][1]));
        }
    }
}

__global__ __launch_bounds__(256, 1)
void gemm_f16_kernel(const float* __restrict__ scale,
                     const float* __restrict__ bias,
                     float* __restrict__ out) {
    extern __shared__ __half smem[];
    __half* As = smem;                       // STAGES * ASTAGE halves
    __half* Bs = smem + STAGES * ASTAGE;     // STAGES * BSTAGE halves

    const int tid  = threadIdx.x;
    const int lane = tid & 31;
    const int warp = tid >> 5;
    const int wm   = (warp >> 2) * 64;
    const int wn   = (warp & 3) * 64;

    // Supertile swizzle: 16 consecutive CTAs share one N-tile.
    const int PN = N_TOTAL / BN;             // 43
    const int GM = 16;                       // M_TOTAL/BM = 32, divisible
    int pid   = blockIdx.x;
    int group = pid / (GM * PN);
    int rem   = pid % (GM * PN);
    const int m0 = (group * GM + (rem % GM)) * BM;
    const int n0 = (rem / GM) * BN;

    float acc[4][8][4];
    #pragma unroll
    for (int i = 0; i < 4; i++)
        #pragma unroll
        for (int j = 0; j < 8; j++)
            #pragma unroll
            for (int r = 0; r < 4; r++) acc[i][j][r] = 0.0f;

    // Tile loader: A 512 + B 1024 16B-chunks per stage; 2 + 4 per thread.
    auto load_tiles = [&](int buf, int kbase) {
        #pragma unroll
        for (int j = 0; j < 2; j++) {
            int c   = tid + j * 256;
            int row = c >> 2;
            int ko  = (c & 3) * 8;
            cp_async16(&As[buf * ASTAGE + row * AST + ko],
                       &g_x[(size_t)(m0 + row) * K_TOTAL + kbase + ko]);
        }
        #pragma unroll
        for (int j = 0; j < 4; j++) {
            int c   = tid + j * 256;
            int row = c >> 2;
            int ko  = (c & 3) * 8;
            cp_async16(&Bs[buf * BSTAGE + row * AST + ko],
                       &g_w[(size_t)(n0 + row) * K_TOTAL + kbase + ko]);
        }
    };

    // Prologue: fill STAGES-1 stages.
    #pragma unroll
    for (int s = 0; s < STAGES - 1; s++) {
        load_tiles(s, s * BK);
        asm volatile("cp.async.commit_group;\n");
    }
    asm volatile("cp.async.wait_group %0;\n" :: "n"(STAGES - 2));
    __syncthreads();

    unsigned int a0[4][4], b0[8][2], a1[4][4], b1[8][2];
    int rs = 0;                 // stage being consumed
    int ws = STAGES - 1;        // stage to fill next
    frag_a_load(a0, &As[0], wm, lane, 0);
    frag_b_load(b0, &Bs[0], wn, lane, 0);

    for (int kt = 0; kt < KT; kt++) {
        // -- half 1: prefetch ks=1 frags, issue gmem loads for stage kt+4 --
        frag_a_load(a1, &As[rs * ASTAGE], wm, lane, 1);
        frag_b_load(b1, &Bs[rs * BSTAGE], wn, lane, 1);
        if (kt + STAGES - 1 < KT) {
            load_tiles(ws, (kt + STAGES - 1) * BK);
        }
        ws = (ws + 1 == STAGES) ? 0 : ws + 1;
        asm volatile("cp.async.commit_group;\n");
        mma_tile(acc, a0, b0);

        // -- half 2: next stage resident, prefetch its ks=0 frags --
        asm volatile("cp.async.wait_group %0;\n" :: "n"(STAGES - 2));
        __syncthreads();
        rs = (rs + 1 == STAGES) ? 0 : rs + 1;
        frag_a_load(a0, &As[rs * ASTAGE], wm, lane, 0);   // garbage on last iter, unused
        frag_b_load(b0, &Bs[rs * BSTAGE], wn, lane, 0);
        mma_tile(acc, a1, b1);
    }

    // --- epilogue: out = acc * scale[n] + bias[n] ---
    const int g = lane >> 2;
    const int t = lane & 3;
    #pragma unroll
    for (int nt = 0; nt < 8; nt++) {
        const int col = n0 + wn + nt * 8 + t * 2;
        const float s0 = __ldg(&scale[col]);
        const float s1 = __ldg(&scale[col + 1]);
        const float bb0 = __ldg(&bias[col]);
        const float bb1 = __ldg(&bias[col + 1]);
        #pragma unroll
        for (int mt = 0; mt < 4; mt++) {
            const int row0 = m0 + wm + mt * 16 + g;
            float2 v0, v1;
            v0.x = acc[mt][nt][0] * s0 + bb0;
            v0.y = acc[mt][nt][1] * s1 + bb1;
            v1.x = acc[mt][nt][2] * s0 + bb0;
            v1.y = acc[mt][nt][3] * s1 + bb1;
            *(float2*)&out[(size_t)row0 * N_TOTAL + col] = v0;
            *(float2*)&out[(size_t)(row0 + 8) * N_TOTAL + col] = v1;
        }
    }
}

// ---------------------------------------------------------------------------
extern "C" void kernel_launch(void* const* d_in, const int* in_sizes, int n_in,
                              void* d_out, int out_size) {
    const float* x     = (const float*)d_in[0];
    const int*   wp    = (const int*)d_in[1];
    const float* scale = (const float*)d_in[2];
    const float* bias  = (const float*)d_in[3];
    float*       out   = (float*)d_out;

    convert_x_kernel<<<8192, 256>>>(x);
    convert_w_kernel<<<11008, 256>>>(wp);

    const int smem_bytes = STAGES * (ASTAGE + BSTAGE) * sizeof(__half);  // 153600
    cudaFuncSetAttribute(gemm_f16_kernel,
                         cudaFuncAttributeMaxDynamicSharedMemorySize, smem_bytes);
    const int grid = (M_TOTAL / BM) * (N_TOTAL / BN);   // 1376
    gemm_f16_kernel<<<grid, 256, smem_bytes>>>(scale, bias, out);
}

// round 7
// speedup vs baseline: 1.1158x; 1.0284x over previous
#include <cuda_runtime.h>
#include <cuda_fp16.h>

#define M_TOTAL 4096
#define N_TOTAL 11008
#define K_TOTAL 4096

// Scratch: fp16 copies of x and unpacked integer weights (exact in fp16).
__device__ __align__(16) __half g_x[(size_t)M_TOTAL * K_TOTAL];   // 33.5 MB
__device__ __align__(16) __half g_w[(size_t)N_TOTAL * K_TOTAL];   // 90.2 MB

// ---------------------------------------------------------------------------
// Pre-pass 1: x fp32 -> fp16 (8 floats / thread)
// ---------------------------------------------------------------------------
__global__ void convert_x_kernel(const float* __restrict__ x) {
    int i = blockIdx.x * blockDim.x + threadIdx.x;
    const float4* xv = (const float4*)x;
    float4 a = xv[2 * i];
    float4 b = xv[2 * i + 1];
    __half2 h0 = __floats2half2_rn(a.x, a.y);
    __half2 h1 = __floats2half2_rn(a.z, a.w);
    __half2 h2 = __floats2half2_rn(b.x, b.y);
    __half2 h3 = __floats2half2_rn(b.z, b.w);
    uint4 u;
    u.x = *(const unsigned int*)&h0;
    u.y = *(const unsigned int*)&h1;
    u.z = *(const unsigned int*)&h2;
    u.w = *(const unsigned int*)&h3;
    ((uint4*)g_x)[i] = u;
}

// ---------------------------------------------------------------------------
// Pre-pass 2: unpack int4 nibbles -> fp16 integers (exact; scale in epilogue)
// ---------------------------------------------------------------------------
__device__ __forceinline__ __half2 unpack_pair(int v) {
    int lo = (v & 15) - 8;
    int hi = ((v >> 4) & 15) - 8;
    return __halves2half2(__int2half_rn(lo), __int2half_rn(hi));
}

__global__ void convert_w_kernel(const int* __restrict__ wp) {
    int i = blockIdx.x * blockDim.x + threadIdx.x;
    int4 p0 = ((const int4*)wp)[2 * i];
    int4 p1 = ((const int4*)wp)[2 * i + 1];
    uint4 u0, u1;
    {
        __half2 h0 = unpack_pair(p0.x), h1 = unpack_pair(p0.y);
        __half2 h2 = unpack_pair(p0.z), h3 = unpack_pair(p0.w);
        u0.x = *(const unsigned int*)&h0; u0.y = *(const unsigned int*)&h1;
        u0.z = *(const unsigned int*)&h2; u0.w = *(const unsigned int*)&h3;
    }
    {
        __half2 h0 = unpack_pair(p1.x), h1 = unpack_pair(p1.y);
        __half2 h2 = unpack_pair(p1.z), h3 = unpack_pair(p1.w);
        u1.x = *(const unsigned int*)&h0; u1.y = *(const unsigned int*)&h1;
        u1.z = *(const unsigned int*)&h2; u1.w = *(const unsigned int*)&h3;
    }
    ((uint4*)g_w)[2 * i]     = u0;
    ((uint4*)g_w)[2 * i + 1] = u1;
}

// ---------------------------------------------------------------------------
// Main GEMM (unchanged from round 6): 128x256x32 tile, 5-stage cp.async,
// GM=16 supertile swizzle. Covers exactly the first 1332 tiles (9 waves).
// ---------------------------------------------------------------------------
#define BM 128
#define BN 256
#define BK 32
#define STAGES 5
#define KT (K_TOTAL / BK)          // 128
#define AST 40
#define ASTAGE (BM * AST)
#define BSTAGE (BN * AST)

#define TOTAL_TILES ((M_TOTAL / BM) * (N_TOTAL / BN))   // 1376
#define MAIN_TILES  1332                                 // 9 * 148
#define TAIL_TILES  (TOTAL_TILES - MAIN_TILES)           // 44

__device__ __forceinline__ void cp_async16(void* smem_p, const void* gmem) {
    unsigned int s = (unsigned int)__cvta_generic_to_shared(smem_p);
    asm volatile("cp.async.cg.shared.global [%0], [%1], 16;\n" :: "r"(s), "l"(gmem));
}

__device__ __forceinline__ void tile_coords(int pid, int& m0, int& n0) {
    const int PN = N_TOTAL / BN;   // 43
    const int GM = 16;
    int group = pid / (GM * PN);
    int rem   = pid % (GM * PN);
    m0 = (group * GM + (rem % GM)) * BM;
    n0 = (rem / GM) * BN;
}

__device__ __forceinline__ void frag_a_load(unsigned int a[4][4],
                                            const __half* A, int wm,
                                            int lane, int ks) {
    #pragma unroll
    for (int mt = 0; mt < 4; mt++) {
        int r  = wm + mt * 16 + (lane & 15);
        int kk = ks * 16 + ((lane >> 4) << 3);
        unsigned int addr = (unsigned int)__cvta_generic_to_shared(&A[r * AST + kk]);
        asm volatile("ldmatrix.sync.aligned.m8n8.x4.shared.b16 {%0,%1,%2,%3}, [%4];"
                     : "=r"(a[mt][0]), "=r"(a[mt][1]), "=r"(a[mt][2]), "=r"(a[mt][3])
                     : "r"(addr));
    }
}

__device__ __forceinline__ void frag_b_load8(unsigned int b[8][2],
                                             const __half* B, int wn,
                                             int lane, int ks) {
    #pragma unroll
    for (int np = 0; np < 4; np++) {
        int r  = wn + np * 16 + (((lane >> 4) & 1) << 3) + (lane & 7);
        int kk = ks * 16 + (((lane >> 3) & 1) << 3);
        unsigned int addr = (unsigned int)__cvta_generic_to_shared(&B[r * AST + kk]);
        asm volatile("ldmatrix.sync.aligned.m8n8.x4.shared.b16 {%0,%1,%2,%3}, [%4];"
                     : "=r"(b[2 * np][0]), "=r"(b[2 * np][1]),
                       "=r"(b[2 * np + 1][0]), "=r"(b[2 * np + 1][1])
                     : "r"(addr));
    }
}

__device__ __forceinline__ void frag_b_load4(unsigned int b[4][2],
                                             const __half* B, int wn,
                                             int lane, int ks) {
    #pragma unroll
    for (int np = 0; np < 2; np++) {
        int r  = wn + np * 16 + (((lane >> 4) & 1) << 3) + (lane & 7);
        int kk = ks * 16 + (((lane >> 3) & 1) << 3);
        unsigned int addr = (unsigned int)__cvta_generic_to_shared(&B[r * AST + kk]);
        asm volatile("ldmatrix.sync.aligned.m8n8.x4.shared.b16 {%0,%1,%2,%3}, [%4];"
                     : "=r"(b[2 * np][0]), "=r"(b[2 * np][1]),
                       "=r"(b[2 * np + 1][0]), "=r"(b[2 * np + 1][1])
                     : "r"(addr));
    }
}

#define MMA16816(acc, a, b)                                                  \
    asm volatile(                                                            \
        "mma.sync.aligned.m16n8k16.row.col.f32.f16.f16.f32 "                 \
        "{%0,%1,%2,%3}, {%4,%5,%6,%7}, {%8,%9}, {%0,%1,%2,%3};"              \
        : "+f"((acc)[0]), "+f"((acc)[1]), "+f"((acc)[2]), "+f"((acc)[3])     \
        : "r"((a)[0]), "r"((a)[1]), "r"((a)[2]), "r"((a)[3]),                \
          "r"((b)[0]), "r"((b)[1]))

__global__ __launch_bounds__(256, 1)
void gemm_f16_kernel(const float* __restrict__ scale,
                     const float* __restrict__ bias,
                     float* __restrict__ out) {
    extern __shared__ __half smem[];
    __half* As = smem;
    __half* Bs = smem + STAGES * ASTAGE;

    const int tid  = threadIdx.x;
    const int lane = tid & 31;
    const int warp = tid >> 5;
    const int wm   = (warp >> 2) * 64;
    const int wn   = (warp & 3) * 64;

    int m0, n0;
    tile_coords(blockIdx.x, m0, n0);

    float acc[4][8][4];
    #pragma unroll
    for (int i = 0; i < 4; i++)
        #pragma unroll
        for (int j = 0; j < 8; j++)
            #pragma unroll
            for (int r = 0; r < 4; r++) acc[i][j][r] = 0.0f;

    auto load_tiles = [&](int buf, int kbase) {
        #pragma unroll
        for (int j = 0; j < 2; j++) {
            int c   = tid + j * 256;
            int row = c >> 2;
            int ko  = (c & 3) * 8;
            cp_async16(&As[buf * ASTAGE + row * AST + ko],
                       &g_x[(size_t)(m0 + row) * K_TOTAL + kbase + ko]);
        }
        #pragma unroll
        for (int j = 0; j < 4; j++) {
            int c   = tid + j * 256;
            int row = c >> 2;
            int ko  = (c & 3) * 8;
            cp_async16(&Bs[buf * BSTAGE + row * AST + ko],
                       &g_w[(size_t)(n0 + row) * K_TOTAL + kbase + ko]);
        }
    };

    #pragma unroll
    for (int s = 0; s < STAGES - 1; s++) {
        load_tiles(s, s * BK);
        asm volatile("cp.async.commit_group;\n");
    }
    asm volatile("cp.async.wait_group %0;\n" :: "n"(STAGES - 2));
    __syncthreads();

    unsigned int a0[4][4], b0[8][2], a1[4][4], b1[8][2];
    int rs = 0;
    int ws = STAGES - 1;
    frag_a_load(a0, &As[0], wm, lane, 0);
    frag_b_load8(b0, &Bs[0], wn, lane, 0);

    for (int kt = 0; kt < KT; kt++) {
        frag_a_load(a1, &As[rs * ASTAGE], wm, lane, 1);
        frag_b_load8(b1, &Bs[rs * BSTAGE], wn, lane, 1);
        if (kt + STAGES - 1 < KT) {
            load_tiles(ws, (kt + STAGES - 1) * BK);
        }
        ws = (ws + 1 == STAGES) ? 0 : ws + 1;
        asm volatile("cp.async.commit_group;\n");
        #pragma unroll
        for (int mt = 0; mt < 4; mt++)
            #pragma unroll
            for (int nt = 0; nt < 8; nt++) MMA16816(acc[mt][nt], a0[mt], b0[nt]);

        asm volatile("cp.async.wait_group %0;\n" :: "n"(STAGES - 2));
        __syncthreads();
        rs = (rs + 1 == STAGES) ? 0 : rs + 1;
        frag_a_load(a0, &As[rs * ASTAGE], wm, lane, 0);
        frag_b_load8(b0, &Bs[rs * BSTAGE], wn, lane, 0);
        #pragma unroll
        for (int mt = 0; mt < 4; mt++)
            #pragma unroll
            for (int nt = 0; nt < 8; nt++) MMA16816(acc[mt][nt], a1[mt], b1[nt]);
    }

    const int g = lane >> 2;
    const int t = lane & 3;
    #pragma unroll
    for (int nt = 0; nt < 8; nt++) {
        const int col = n0 + wn + nt * 8 + t * 2;
        const float s0 = __ldg(&scale[col]);
        const float s1 = __ldg(&scale[col + 1]);
        const float bb0 = __ldg(&bias[col]);
        const float bb1 = __ldg(&bias[col + 1]);
        #pragma unroll
        for (int mt = 0; mt < 4; mt++) {
            const int row0 = m0 + wm + mt * 16 + g;
            float2 v0, v1;
            v0.x = acc[mt][nt][0] * s0 + bb0;
            v0.y = acc[mt][nt][1] * s1 + bb1;
            v1.x = acc[mt][nt][2] * s0 + bb0;
            v1.y = acc[mt][nt][3] * s1 + bb1;
            *(float2*)&out[(size_t)row0 * N_TOTAL + col] = v0;
            *(float2*)&out[(size_t)(row0 + 8) * N_TOTAL + col] = v1;
        }
    }
}

// ---------------------------------------------------------------------------
// Tail GEMM: the last 44 tiles (128x256) split into 88 half-tiles (128x128).
// Warp tile 64x32 (2x4 warps), 4-stage pipeline (round-3 proven shape).
// ---------------------------------------------------------------------------
#define TBN 128
#define TSTAGES 4
#define TBSTAGE (TBN * AST)

__global__ __launch_bounds__(256, 1)
void gemm_f16_tail_kernel(const float* __restrict__ scale,
                          const float* __restrict__ bias,
                          float* __restrict__ out) {
    extern __shared__ __half smem[];
    __half* As = smem;
    __half* Bs = smem + TSTAGES * ASTAGE;

    const int tid  = threadIdx.x;
    const int lane = tid & 31;
    const int warp = tid >> 5;
    const int wm   = (warp >> 2) * 64;
    const int wn   = (warp & 3) * 32;

    int m0, n0;
    tile_coords(MAIN_TILES + (blockIdx.x >> 1), m0, n0);
    n0 += (blockIdx.x & 1) * TBN;

    float acc[4][4][4];
    #pragma unroll
    for (int i = 0; i < 4; i++)
        #pragma unroll
        for (int j = 0; j < 4; j++)
            #pragma unroll
            for (int r = 0; r < 4; r++) acc[i][j][r] = 0.0f;

    auto load_tiles = [&](int buf, int kbase) {
        #pragma unroll
        for (int j = 0; j < 2; j++) {
            int c   = tid + j * 256;
            int row = c >> 2;
            int ko  = (c & 3) * 8;
            cp_async16(&As[buf * ASTAGE + row * AST + ko],
                       &g_x[(size_t)(m0 + row) * K_TOTAL + kbase + ko]);
            cp_async16(&Bs[buf * TBSTAGE + row * AST + ko],
                       &g_w[(size_t)(n0 + row) * K_TOTAL + kbase + ko]);
        }
    };

    #pragma unroll
    for (int s = 0; s < TSTAGES - 1; s++) {
        load_tiles(s, s * BK);
        asm volatile("cp.async.commit_group;\n");
    }
    asm volatile("cp.async.wait_group %0;\n" :: "n"(TSTAGES - 2));
    __syncthreads();

    unsigned int a0[4][4], b0[4][2], a1[4][4], b1[4][2];
    int rs = 0;
    frag_a_load(a0, &As[0], wm, lane, 0);
    frag_b_load4(b0, &Bs[0], wn, lane, 0);

    for (int kt = 0; kt < KT; kt++) {
        frag_a_load(a1, &As[rs * ASTAGE], wm, lane, 1);
        frag_b_load4(b1, &Bs[rs * TBSTAGE], wn, lane, 1);
        if (kt + TSTAGES - 1 < KT) {
            load_tiles((rs + TSTAGES - 1) & (TSTAGES - 1), (kt + TSTAGES - 1) * BK);
        }
        asm volatile("cp.async.commit_group;\n");
        #pragma unroll
        for (int mt = 0; mt < 4; mt++)
            #pragma unroll
            for (int nt = 0; nt < 4; nt++) MMA16816(acc[mt][nt], a0[mt], b0[nt]);

        asm volatile("cp.async.wait_group %0;\n" :: "n"(TSTAGES - 2));
        __syncthreads();
        rs = (rs + 1) & (TSTAGES - 1);
        frag_a_load(a0, &As[rs * ASTAGE], wm, lane, 0);
        frag_b_load4(b0, &Bs[rs * TBSTAGE], wn, lane, 0);
        #pragma unroll
        for (int mt = 0; mt < 4; mt++)
            #pragma unroll
            for (int nt = 0; nt < 4; nt++) MMA16816(acc[mt][nt], a1[mt], b1[nt]);
    }

    const int g = lane >> 2;
    const int t = lane & 3;
    #pragma unroll
    for (int nt = 0; nt < 4; nt++) {
        const int col = n0 + wn + nt * 8 + t * 2;
        const float s0 = __ldg(&scale[col]);
        const float s1 = __ldg(&scale[col + 1]);
        const float bb0 = __ldg(&bias[col]);
        const float bb1 = __ldg(&bias[col + 1]);
        #pragma unroll
        for (int mt = 0; mt < 4; mt++) {
            const int row0 = m0 + wm + mt * 16 + g;
            float2 v0, v1;
            v0.x = acc[mt][nt][0] * s0 + bb0;
            v0.y = acc[mt][nt][1] * s1 + bb1;
            v1.x = acc[mt][nt][2] * s0 + bb0;
            v1.y = acc[mt][nt][3] * s1 + bb1;
            *(float2*)&out[(size_t)row0 * N_TOTAL + col] = v0;
            *(float2*)&out[(size_t)(row0 + 8) * N_TOTAL + col] = v1;
        }
    }
}

// ---------------------------------------------------------------------------
extern "C" void kernel_launch(void* const* d_in, const int* in_sizes, int n_in,
                              void* d_out, int out_size) {
    const float* x     = (const float*)d_in[0];
    const int*   wp    = (const int*)d_in[1];
    const float* scale = (const float*)d_in[2];
    const float* bias  = (const float*)d_in[3];
    float*       out   = (float*)d_out;

    convert_x_kernel<<<8192, 256>>>(x);
    convert_w_kernel<<<11008, 256>>>(wp);

    const int smem_main = STAGES * (ASTAGE + BSTAGE) * sizeof(__half);    // 153600
    cudaFuncSetAttribute(gemm_f16_kernel,
                         cudaFuncAttributeMaxDynamicSharedMemorySize, smem_main);
    gemm_f16_kernel<<<MAIN_TILES, 256, smem_main>>>(scale, bias, out);

    const int smem_tail = TSTAGES * (ASTAGE + TBSTAGE) * sizeof(__half);  // 81920
    cudaFuncSetAttribute(gemm_f16_tail_kernel,
                         cudaFuncAttributeMaxDynamicSharedMemorySize, smem_tail);
    gemm_f16_tail_kernel<<<2 * TAIL_TILES, 256, smem_tail>>>(scale, bias, out);
}

// round 8
// speedup vs baseline: 1.1334x; 1.0157x over previous
#include <cuda_runtime.h>
#include <cuda_fp16.h>

#define M_TOTAL 4096
#define N_TOTAL 11008
#define K_TOTAL 4096

// Scratch: fp16 copies of x and unpacked integer weights (exact in fp16).
__device__ __align__(16) __half g_x[(size_t)M_TOTAL * K_TOTAL];   // 33.5 MB
__device__ __align__(16) __half g_w[(size_t)N_TOTAL * K_TOTAL];   // 90.2 MB

#define BM 128
#define BN 256
#define BK 32
#define STAGES 5
#define KT (K_TOTAL / BK)          // 128
#define AST 40
#define ASTAGE (BM * AST)
#define BSTAGE (BN * AST)

#define TOTAL_TILES ((M_TOTAL / BM) * (N_TOTAL / BN))   // 1376
#define MAIN_TILES  1332                                 // 9 * 148
#define TAIL_TILES  (TOTAL_TILES - MAIN_TILES)           // 44
#define KSPLITS     3
#define PART_CTAS   (TAIL_TILES * KSPLITS)               // 132

// fp32 partials for the K-split tail: [split][tile][128][256]
__device__ __align__(16) float g_part[(size_t)KSPLITS * TAIL_TILES * BM * BN]; // 17.3MB

// ---------------------------------------------------------------------------
// Pre-pass 1: x fp32 -> fp16
// ---------------------------------------------------------------------------
__global__ void convert_x_kernel(const float* __restrict__ x) {
    int i = blockIdx.x * blockDim.x + threadIdx.x;
    const float4* xv = (const float4*)x;
    float4 a = xv[2 * i];
    float4 b = xv[2 * i + 1];
    __half2 h0 = __floats2half2_rn(a.x, a.y);
    __half2 h1 = __floats2half2_rn(a.z, a.w);
    __half2 h2 = __floats2half2_rn(b.x, b.y);
    __half2 h3 = __floats2half2_rn(b.z, b.w);
    uint4 u;
    u.x = *(const unsigned int*)&h0;
    u.y = *(const unsigned int*)&h1;
    u.z = *(const unsigned int*)&h2;
    u.w = *(const unsigned int*)&h3;
    ((uint4*)g_x)[i] = u;
}

// ---------------------------------------------------------------------------
// Pre-pass 2: unpack int4 nibbles -> fp16 integers (exact; scale in epilogue)
// ---------------------------------------------------------------------------
__device__ __forceinline__ __half2 unpack_pair(int v) {
    int lo = (v & 15) - 8;
    int hi = ((v >> 4) & 15) - 8;
    return __halves2half2(__int2half_rn(lo), __int2half_rn(hi));
}

__global__ void convert_w_kernel(const int* __restrict__ wp) {
    int i = blockIdx.x * blockDim.x + threadIdx.x;
    int4 p0 = ((const int4*)wp)[2 * i];
    int4 p1 = ((const int4*)wp)[2 * i + 1];
    uint4 u0, u1;
    {
        __half2 h0 = unpack_pair(p0.x), h1 = unpack_pair(p0.y);
        __half2 h2 = unpack_pair(p0.z), h3 = unpack_pair(p0.w);
        u0.x = *(const unsigned int*)&h0; u0.y = *(const unsigned int*)&h1;
        u0.z = *(const unsigned int*)&h2; u0.w = *(const unsigned int*)&h3;
    }
    {
        __half2 h0 = unpack_pair(p1.x), h1 = unpack_pair(p1.y);
        __half2 h2 = unpack_pair(p1.z), h3 = unpack_pair(p1.w);
        u1.x = *(const unsigned int*)&h0; u1.y = *(const unsigned int*)&h1;
        u1.z = *(const unsigned int*)&h2; u1.w = *(const unsigned int*)&h3;
    }
    ((uint4*)g_w)[2 * i]     = u0;
    ((uint4*)g_w)[2 * i + 1] = u1;
}

// ---------------------------------------------------------------------------
// GEMM machinery (identical to round 6/7 main kernel)
// ---------------------------------------------------------------------------
__device__ __forceinline__ void cp_async16(void* smem_p, const void* gmem) {
    unsigned int s = (unsigned int)__cvta_generic_to_shared(smem_p);
    asm volatile("cp.async.cg.shared.global [%0], [%1], 16;\n" :: "r"(s), "l"(gmem));
}

__device__ __forceinline__ void tile_coords(int pid, int& m0, int& n0) {
    const int PN = N_TOTAL / BN;   // 43
    const int GM = 16;
    int group = pid / (GM * PN);
    int rem   = pid % (GM * PN);
    m0 = (group * GM + (rem % GM)) * BM;
    n0 = (rem / GM) * BN;
}

__device__ __forceinline__ void frag_a_load(unsigned int a[4][4],
                                            const __half* A, int wm,
                                            int lane, int ks) {
    #pragma unroll
    for (int mt = 0; mt < 4; mt++) {
        int r  = wm + mt * 16 + (lane & 15);
        int kk = ks * 16 + ((lane >> 4) << 3);
        unsigned int addr = (unsigned int)__cvta_generic_to_shared(&A[r * AST + kk]);
        asm volatile("ldmatrix.sync.aligned.m8n8.x4.shared.b16 {%0,%1,%2,%3}, [%4];"
                     : "=r"(a[mt][0]), "=r"(a[mt][1]), "=r"(a[mt][2]), "=r"(a[mt][3])
                     : "r"(addr));
    }
}

__device__ __forceinline__ void frag_b_load8(unsigned int b[8][2],
                                             const __half* B, int wn,
                                             int lane, int ks) {
    #pragma unroll
    for (int np = 0; np < 4; np++) {
        int r  = wn + np * 16 + (((lane >> 4) & 1) << 3) + (lane & 7);
        int kk = ks * 16 + (((lane >> 3) & 1) << 3);
        unsigned int addr = (unsigned int)__cvta_generic_to_shared(&B[r * AST + kk]);
        asm volatile("ldmatrix.sync.aligned.m8n8.x4.shared.b16 {%0,%1,%2,%3}, [%4];"
                     : "=r"(b[2 * np][0]), "=r"(b[2 * np][1]),
                       "=r"(b[2 * np + 1][0]), "=r"(b[2 * np + 1][1])
                     : "r"(addr));
    }
}

#define MMA16816(acc, a, b)                                                  \
    asm volatile(                                                            \
        "mma.sync.aligned.m16n8k16.row.col.f32.f16.f16.f32 "                 \
        "{%0,%1,%2,%3}, {%4,%5,%6,%7}, {%8,%9}, {%0,%1,%2,%3};"              \
        : "+f"((acc)[0]), "+f"((acc)[1]), "+f"((acc)[2]), "+f"((acc)[3])     \
        : "r"((a)[0]), "r"((a)[1]), "r"((a)[2]), "r"((a)[3]),                \
          "r"((b)[0]), "r"((b)[1]))

// Shared GEMM mainloop body. Called with compile-time ktiles=KT for the main
// tiles (preserves round-6 codegen) and runtime ktiles for K-split partials.
__device__ __forceinline__ void gemm_body(__half* As, __half* Bs,
                                          int m0, int n0, int kbase, int ktiles,
                                          int tid, int lane, int wm, int wn,
                                          float acc[4][8][4]) {
    auto load_tiles = [&](int buf, int koff) {
        #pragma unroll
        for (int j = 0; j < 2; j++) {
            int c   = tid + j * 256;
            int row = c >> 2;
            int ko  = (c & 3) * 8;
            cp_async16(&As[buf * ASTAGE + row * AST + ko],
                       &g_x[(size_t)(m0 + row) * K_TOTAL + koff + ko]);
        }
        #pragma unroll
        for (int j = 0; j < 4; j++) {
            int c   = tid + j * 256;
            int row = c >> 2;
            int ko  = (c & 3) * 8;
            cp_async16(&Bs[buf * BSTAGE + row * AST + ko],
                       &g_w[(size_t)(n0 + row) * K_TOTAL + koff + ko]);
        }
    };

    #pragma unroll
    for (int s = 0; s < STAGES - 1; s++) {
        load_tiles(s, kbase + s * BK);
        asm volatile("cp.async.commit_group;\n");
    }
    asm volatile("cp.async.wait_group %0;\n" :: "n"(STAGES - 2));
    __syncthreads();

    unsigned int a0[4][4], b0[8][2], a1[4][4], b1[8][2];
    int rs = 0;
    int ws = STAGES - 1;
    frag_a_load(a0, &As[0], wm, lane, 0);
    frag_b_load8(b0, &Bs[0], wn, lane, 0);

    for (int kt = 0; kt < ktiles; kt++) {
        frag_a_load(a1, &As[rs * ASTAGE], wm, lane, 1);
        frag_b_load8(b1, &Bs[rs * BSTAGE], wn, lane, 1);
        if (kt + STAGES - 1 < ktiles) {
            load_tiles(ws, kbase + (kt + STAGES - 1) * BK);
        }
        ws = (ws + 1 == STAGES) ? 0 : ws + 1;
        asm volatile("cp.async.commit_group;\n");
        #pragma unroll
        for (int mt = 0; mt < 4; mt++)
            #pragma unroll
            for (int nt = 0; nt < 8; nt++) MMA16816(acc[mt][nt], a0[mt], b0[nt]);

        asm volatile("cp.async.wait_group %0;\n" :: "n"(STAGES - 2));
        __syncthreads();
        rs = (rs + 1 == STAGES) ? 0 : rs + 1;
        frag_a_load(a0, &As[rs * ASTAGE], wm, lane, 0);
        frag_b_load8(b0, &Bs[rs * BSTAGE], wn, lane, 0);
        #pragma unroll
        for (int mt = 0; mt < 4; mt++)
            #pragma unroll
            for (int nt = 0; nt < 8; nt++) MMA16816(acc[mt][nt], a1[mt], b1[nt]);
    }
}

// ---------------------------------------------------------------------------
// Combined GEMM: blocks [0, MAIN_TILES) do full tiles -> out (scale+bias).
// Blocks [MAIN_TILES, MAIN_TILES+PART_CTAS) do K-split tail partials -> g_part.
// ---------------------------------------------------------------------------
__global__ __launch_bounds__(256, 1)
void gemm_f16_kernel(const float* __restrict__ scale,
                     const float* __restrict__ bias,
                     float* __restrict__ out) {
    extern __shared__ __half smem[];
    __half* As = smem;
    __half* Bs = smem + STAGES * ASTAGE;

    const int tid  = threadIdx.x;
    const int lane = tid & 31;
    const int warp = tid >> 5;
    const int wm   = (warp >> 2) * 64;
    const int wn   = (warp & 3) * 64;

    float acc[4][8][4];
    #pragma unroll
    for (int i = 0; i < 4; i++)
        #pragma unroll
        for (int j = 0; j < 8; j++)
            #pragma unroll
            for (int r = 0; r < 4; r++) acc[i][j][r] = 0.0f;

    const int g = lane >> 2;
    const int t = lane & 3;

    if (blockIdx.x < MAIN_TILES) {
        int m0, n0;
        tile_coords(blockIdx.x, m0, n0);
        gemm_body(As, Bs, m0, n0, 0, KT, tid, lane, wm, wn, acc);

        #pragma unroll
        for (int nt = 0; nt < 8; nt++) {
            const int col = n0 + wn + nt * 8 + t * 2;
            const float s0 = __ldg(&scale[col]);
            const float s1 = __ldg(&scale[col + 1]);
            const float bb0 = __ldg(&bias[col]);
            const float bb1 = __ldg(&bias[col + 1]);
            #pragma unroll
            for (int mt = 0; mt < 4; mt++) {
                const int row0 = m0 + wm + mt * 16 + g;
                float2 v0, v1;
                v0.x = acc[mt][nt][0] * s0 + bb0;
                v0.y = acc[mt][nt][1] * s1 + bb1;
                v1.x = acc[mt][nt][2] * s0 + bb0;
                v1.y = acc[mt][nt][3] * s1 + bb1;
                *(float2*)&out[(size_t)row0 * N_TOTAL + col] = v0;
                *(float2*)&out[(size_t)(row0 + 8) * N_TOTAL + col] = v1;
            }
        }
    } else {
        // K-split tail partial: 3 splits of 43/43/42 ktiles.
        const int pidx  = blockIdx.x - MAIN_TILES;   // 0..131
        const int tile  = pidx % TAIL_TILES;         // 0..43
        const int split = pidx / TAIL_TILES;         // 0..2
        const int kstart = (split == 0) ? 0 : (split == 1 ? 43 : 86);
        const int kcount = (split == 2) ? 42 : 43;

        int m0, n0;
        tile_coords(MAIN_TILES + tile, m0, n0);
        gemm_body(As, Bs, m0, n0, kstart * BK, kcount, tid, lane, wm, wn, acc);

        float* dst = &g_part[((size_t)split * TAIL_TILES + tile) * (BM * BN)];
        #pragma unroll
        for (int nt = 0; nt < 8; nt++) {
            const int col = wn + nt * 8 + t * 2;
            #pragma unroll
            for (int mt = 0; mt < 4; mt++) {
                const int row0 = wm + mt * 16 + g;
                *(float2*)&dst[row0 * BN + col] =
                    make_float2(acc[mt][nt][0], acc[mt][nt][1]);
                *(float2*)&dst[(row0 + 8) * BN + col] =
                    make_float2(acc[mt][nt][2], acc[mt][nt][3]);
            }
        }
    }
}

// ---------------------------------------------------------------------------
// Tail reduce: out = (p0 + p1 + p2) * scale + bias for the 44 tail tiles.
// One float4 per thread; 360448 float4 total.
// ---------------------------------------------------------------------------
__global__ void tail_reduce_kernel(const float* __restrict__ scale,
                                   const float* __restrict__ bias,
                                   float* __restrict__ out) {
    const int i4 = blockIdx.x * blockDim.x + threadIdx.x;   // float4 index
    const int PER_TILE4 = BM * BN / 4;                      // 8192
    const int tile = i4 / PER_TILE4;
    const int rem  = i4 % PER_TILE4;
    const int row  = rem / (BN / 4);
    const int c4   = rem % (BN / 4);

    const size_t ss = (size_t)TAIL_TILES * BM * BN / 4;     // split stride (float4)
    const size_t base = (size_t)tile * PER_TILE4 + rem;
    const float4* p = (const float4*)g_part;
    float4 v0 = p[base];
    float4 v1 = p[base + ss];
    float4 v2 = p[base + 2 * ss];

    int m0, n0;
    tile_coords(MAIN_TILES + tile, m0, n0);
    const int col = n0 + c4 * 4;
    const float4 sc = *(const float4*)&scale[col];
    const float4 bb = *(const float4*)&bias[col];

    float4 r;
    r.x = (v0.x + v1.x + v2.x) * sc.x + bb.x;
    r.y = (v0.y + v1.y + v2.y) * sc.y + bb.y;
    r.z = (v0.z + v1.z + v2.z) * sc.z + bb.z;
    r.w = (v0.w + v1.w + v2.w) * sc.w + bb.w;
    *(float4*)&out[(size_t)(m0 + row) * N_TOTAL + col] = r;
}

// ---------------------------------------------------------------------------
extern "C" void kernel_launch(void* const* d_in, const int* in_sizes, int n_in,
                              void* d_out, int out_size) {
    const float* x     = (const float*)d_in[0];
    const int*   wp    = (const int*)d_in[1];
    const float* scale = (const float*)d_in[2];
    const float* bias  = (const float*)d_in[3];
    float*       out   = (float*)d_out;

    convert_x_kernel<<<8192, 256>>>(x);
    convert_w_kernel<<<11008, 256>>>(wp);

    const int smem_bytes = STAGES * (ASTAGE + BSTAGE) * sizeof(__half);  // 153600
    cudaFuncSetAttribute(gemm_f16_kernel,
                         cudaFuncAttributeMaxDynamicSharedMemorySize, smem_bytes);
    gemm_f16_kernel<<<MAIN_TILES + PART_CTAS, 256, smem_bytes>>>(scale, bias, out);

    // 44 * 128 * 256 / 4 = 360448 float4 -> 1408 blocks of 256
    tail_reduce_kernel<<<1408, 256>>>(scale, bias, out);
}